// round 7
// baseline (speedup 1.0000x reference)
#include <cuda_runtime.h>
#include <cuda_fp16.h>
#include <cstdint>

#define HW_    3136
#define KTOT_  1152
#define NCHUNK 36          // 9 taps * 4 c-chunks of 32
#define NPIX_  112         // pixels per block tile = 2 image rows

// effective conv weights (fp16), [e][o][k], k = tap*128 + c (tap-major, plain c order)
__device__ __align__(16) __half g_Wh[8 * 128 * KTOT_];
// packed x: [b][window (8 of 16ch)][58*58 px][16 halves, permuted {0,1,8,9,2,3,10,11,4,5,12,13,6,7,14,15}]
__device__ __align__(16) __half g_xq[(size_t)32 * 8 * 3364 * 16];

__device__ __forceinline__ uint32_t smem_u32(const void* p) {
    uint32_t a;
    asm("{ .reg .u64 t; cvta.to.shared.u64 t, %1; cvt.u32.u64 %0, t; }" : "=r"(a) : "l"(p));
    return a;
}
#define CP_ASYNC16(dst, src) \
    asm volatile("cp.async.cg.shared.global [%0], [%1], 16;" :: "r"(dst), "l"(src))
#define CP_COMMIT()  asm volatile("cp.async.commit_group;")
#define CP_WAIT2()   asm volatile("cp.async.wait_group 2;")

__device__ __forceinline__ void mma16816(float* d, const uint32_t* a, uint32_t b0, uint32_t b1) {
    asm volatile("mma.sync.aligned.m16n8k16.row.col.f32.f16.f16.f32 "
                 "{%0,%1,%2,%3}, {%4,%5,%6,%7}, {%8,%9}, {%0,%1,%2,%3};"
                 : "+f"(d[0]), "+f"(d[1]), "+f"(d[2]), "+f"(d[3])
                 : "r"(a[0]), "r"(a[1]), "r"(a[2]), "r"(a[3]), "r"(b0), "r"(b1));
}

// ---------------- Prep: pad + fp16 + permuted 16-channel pack ----------------
__global__ __launch_bounds__(256) void pack_kernel(const float* __restrict__ x) {
    const int wg = blockIdx.x;   // window 0..7
    const int b  = blockIdx.y;   // 0..31
    const float* xb = x + ((size_t)b * 128 + wg * 16) * HW_;
    uint32_t* dst = (uint32_t*)(g_xq + ((size_t)(b * 8 + wg)) * 3364 * 16);
    const int P[16] = {0, 1, 8, 9, 2, 3, 10, 11, 4, 5, 12, 13, 6, 7, 14, 15};
    for (int i = threadIdx.x; i < 3364; i += 256) {
        int r = i / 58;
        int c = i - r * 58;
        bool in = ((unsigned)(r - 1) < 56u) && ((unsigned)(c - 1) < 56u);
        int q = (r - 1) * 56 + (c - 1);
        uint32_t v[8];
#pragma unroll
        for (int s = 0; s < 8; s++) {
            float f0 = in ? xb[(size_t)P[2 * s] * HW_ + q] : 0.f;
            float f1 = in ? xb[(size_t)P[2 * s + 1] * HW_ + q] : 0.f;
            __half2 hp = __floats2half2_rn(f0, f1);
            v[s] = *(uint32_t*)&hp;
        }
        uint4 u0 = make_uint4(v[0], v[1], v[2], v[3]);
        uint4 u1 = make_uint4(v[4], v[5], v[6], v[7]);
        *(uint4*)(dst + (size_t)i * 8)     = u0;
        *(uint4*)(dst + (size_t)i * 8 + 4) = u1;
    }
}

// ---------------- Kernel A: build W_eff -> fp16, tap-major k ----------------
__global__ __launch_bounds__(256) void build_weff_kernel(
    const float* __restrict__ wspec,   // [8][128][1152] (cdd = c*9 + tap)
    const float* __restrict__ wch)     // [8][128][256]
{
    const int e  = blockIdx.y;
    const int n0 = blockIdx.x * 128;

    __shared__ float As[8][128];
    __shared__ float Bs[8][128];

    const int t  = threadIdx.x;
    const int tm = t >> 4;
    const int tn = t & 15;

    float acc[8][8];
#pragma unroll
    for (int i = 0; i < 8; i++)
#pragma unroll
        for (int j = 0; j < 8; j++) acc[i][j] = 0.f;

    for (int kt = 0; kt < 16; ++kt) {
#pragma unroll
        for (int i = 0; i < 4; i++) {
            int idx = t + i * 256;
            int kl  = idx >> 7;
            int nl  = idx & 127;
            As[kl][nl] = wspec[(e * 128 + kt * 8 + kl) * 1152 + n0 + nl];
            Bs[kl][nl] = wch[(e * 128 + nl) * 256 + 128 + kt * 8 + kl];
        }
        __syncthreads();
#pragma unroll
        for (int kk = 0; kk < 8; kk++) {
            float a[8], bv[8];
            *(float4*)&a[0]  = *(const float4*)&As[kk][tm * 4];
            *(float4*)&a[4]  = *(const float4*)&As[kk][64 + tm * 4];
            *(float4*)&bv[0] = *(const float4*)&Bs[kk][tn * 4];
            *(float4*)&bv[4] = *(const float4*)&Bs[kk][64 + tn * 4];
#pragma unroll
            for (int i = 0; i < 8; i++)
#pragma unroll
                for (int j = 0; j < 8; j++) acc[i][j] += a[i] * bv[j];
        }
        __syncthreads();
    }

#pragma unroll
    for (int mi = 0; mi < 8; mi++) {
        int mrow = (mi < 4) ? (tm * 4 + mi) : (64 + tm * 4 + mi - 4);
        int cdd  = n0 + mrow;
        int cc   = cdd / 9;
        int tap  = cdd - cc * 9;
        bool center = (tap == 4);
        int kidx = tap * 128 + cc;
#pragma unroll
        for (int j = 0; j < 8; j++) {
            int o = (j < 4) ? (tn * 4 + j) : (64 + tn * 4 + j - 4);
            float v = acc[mi][j];
            if (center) v += wch[(e * 128 + o) * 256 + cc];
            g_Wh[((size_t)(e * 128 + o)) * KTOT_ + kidx] = __float2half_rn(v);
        }
    }
}

// ---------------- Kernel B: fp16 mma.sync, A-in-regs, B 16B cp.async ring ----------------
// B smem per stage: [window kh2 (2)][px (112)][16 permuted halves] = 7168 B
#define B_BYTES   7168
#define NSTAGE    4
#define SMEM_TOTAL (NSTAGE * B_BYTES)                // 28672
#define B_OFF(buf) ((buf) * B_BYTES)

__global__ __launch_bounds__(512) void conv_mma_kernel(
    const int* __restrict__ gate,     // [32][2]
    float*     __restrict__ out)      // [32][2][128][56][56]
{
    extern __shared__ char smem[];
    const uint32_t sb = smem_u32(smem);

    const int tid  = threadIdx.x;
    const int wid  = tid >> 5;
    const int lane = tid & 31;
    const int g    = lane >> 2;
    const int tq   = lane & 3;
    const int b    = blockIdx.y;
    const int n0   = blockIdx.x * NPIX_;
    const int h0   = blockIdx.x * 2;

    const int ex   = wid >> 3;
    const int e0   = gate[2 * b];
    const int e1   = gate[2 * b + 1];
    const int e    = ex ? e1 : e0;

    const __half* Wme = g_Wh + (size_t)e * 128 * KTOT_;
    const __half* xqb = g_xq + (size_t)b * 8 * 3364 * 16;

    const int wg = wid & 7;
    const int mo = (wg >> 1) * 32;
    const int po = (wg & 1) * 56;

    float acc[2][7][4];
#pragma unroll
    for (int mt = 0; mt < 2; mt++)
#pragma unroll
        for (int j = 0; j < 7; j++)
#pragma unroll
            for (int q = 0; q < 4; q++) acc[mt][j][q] = 0.f;

    // ---- B fill: 1 cp.async.16 per thread (448 active) ----
    const bool fv  = (tid < 448);
    const int fw   = tid / 224;            // window 0/1
    const int fr   = tid - fw * 224;
    const int fpx  = fr >> 1;
    const int fh   = fr & 1;
    const int fpr  = (fpx >= 56);
    const int fpw  = fpx - 56 * fpr;

    auto fillB = [&](int buf, int ch) {
        if (fv) {
            const int tap = ch >> 2;
            const int dy  = tap / 3;
            const int dx  = tap - 3 * dy;
            const int poff = (h0 + fpr + dy) * 58 + (fpw + dx);
            const int w16  = ((ch & 3) << 1) + fw;
            const __half* src = xqb + ((size_t)w16 * 3364 + poff) * 16 + fh * 8;
            uint32_t d = sb + B_OFF(buf) + fw * 3584 + fpx * 32 + fh * 16;
            CP_ASYNC16(d, src);
        }
    };

    // ---- A load: 16 LDG.32 -> canonical fragments, double-buffered in regs ----
    auto loadA = [&](uint32_t (&a)[2][2][4], int ch) {
        const int tap = ch >> 2;
        const int kb  = tap * 128 + ((ch & 3) << 5) + 2 * tq;
        const __half* base = Wme + (size_t)(mo + g) * KTOT_ + kb;
#pragma unroll
        for (int mt = 0; mt < 2; mt++)
#pragma unroll
            for (int kh2 = 0; kh2 < 2; kh2++) {
                const __half* p = base + (size_t)mt * 16 * KTOT_ + kh2 * 16;
                a[mt][kh2][0] = *(const uint32_t*)(p);
                a[mt][kh2][1] = *(const uint32_t*)(p + 8 * KTOT_);
                a[mt][kh2][2] = *(const uint32_t*)(p + 8);
                a[mt][kh2][3] = *(const uint32_t*)(p + 8 * KTOT_ + 8);
            }
    };

    auto computeStage = [&](int buf, uint32_t (&a)[2][2][4]) {
        const char* Bb = smem + B_OFF(buf);
#pragma unroll
        for (int kh2 = 0; kh2 < 2; kh2++) {
#pragma unroll
            for (int j = 0; j < 7; j++) {
                const int col = po + j * 8 + g;
                uint2 b01 = *(const uint2*)(Bb + kh2 * 3584 + col * 32 + tq * 8);
#pragma unroll
                for (int mt = 0; mt < 2; mt++)
                    mma16816(acc[mt][j], a[mt][kh2], b01.x, b01.y);
            }
        }
    };

    uint32_t aA[2][2][4], aB[2][2][4];

    // ---- prologue: 3 B stages in flight, A regs for stage 0 ----
    fillB(0, 0); CP_COMMIT();
    fillB(1, 1); CP_COMMIT();
    fillB(2, 2); CP_COMMIT();
    loadA(aA, 0);

    int buf = 0;
    for (int ch = 0; ch < NCHUNK; ch += 2) {
        // even stage
        CP_WAIT2();
        __syncthreads();
        if (ch + 3 < NCHUNK) fillB((buf + 3) & 3, ch + 3);
        CP_COMMIT();
        loadA(aB, ch + 1);
        computeStage(buf, aA);
        buf = (buf + 1) & 3;

        // odd stage
        CP_WAIT2();
        __syncthreads();
        if (ch + 4 < NCHUNK) fillB((buf + 3) & 3, ch + 4);
        CP_COMMIT();
        if (ch + 2 < NCHUNK) loadA(aA, ch + 2);
        computeStage(buf, aB);
        buf = (buf + 1) & 3;
    }

    // ---- epilogue ----
    float* ob = out + (size_t)(2 * b + ex) * 128 * HW_;
#pragma unroll
    for (int mt = 0; mt < 2; mt++) {
#pragma unroll
        for (int j = 0; j < 7; j++) {
            int pc = n0 + po + j * 8 + tq * 2;
            int row0 = mo + mt * 16 + g;
            float2 v0 = make_float2(acc[mt][j][0], acc[mt][j][1]);
            float2 v1 = make_float2(acc[mt][j][2], acc[mt][j][3]);
            *(float2*)(ob + (size_t)row0 * HW_ + pc) = v0;
            *(float2*)(ob + (size_t)(row0 + 8) * HW_ + pc) = v1;
        }
    }
}

// ----------------------------------------------------------------------------
extern "C" void kernel_launch(void* const* d_in, const int* in_sizes, int n_in,
                              void* d_out, int out_size) {
    const float* x     = (const float*)d_in[0];   // [32,128,56,56] f32
    const int*   gate  = (const int*)  d_in[1];   // [32,2] i32
    const float* wspec = (const float*)d_in[2];   // [8,128,128,3,3] f32
    const float* wch   = (const float*)d_in[3];   // [8,128,256,1,1] f32
    float* out = (float*)d_out;                   // [32,2,128,56,56] f32

    cudaFuncSetAttribute(conv_mma_kernel,
                         cudaFuncAttributeMaxDynamicSharedMemorySize, SMEM_TOTAL);

    pack_kernel<<<dim3(8, 32), 256>>>(x);
    build_weff_kernel<<<dim3(9, 8), 256>>>(wspec, wch);
    conv_mma_kernel<<<dim3(28, 32), 512, SMEM_TOTAL>>>(gate, out);
}

// round 8
// speedup vs baseline: 1.5345x; 1.5345x over previous
#include <cuda_runtime.h>
#include <cuda_fp16.h>
#include <cstdint>

#define HW_    3136
#define KTOT_  1152
#define NCHUNK 36          // 9 taps * 4 c-chunks of 32
#define NPIX_  112         // pixels per block tile = 2 image rows

// effective conv weights (fp16), [e][o][k], k = tap*128 + c (tap-major)
__device__ __align__(16) __half g_Wh[8 * 128 * KTOT_];
// packed x: [b][window (8 of 16ch)][58*58 px][16 halves, permuted {0,1,8,9,2,3,10,11,4,5,12,13,6,7,14,15}]
__device__ __align__(16) __half g_xq[(size_t)32 * 8 * 3364 * 16];

__device__ __forceinline__ uint32_t smem_u32(const void* p) {
    uint32_t a;
    asm("{ .reg .u64 t; cvta.to.shared.u64 t, %1; cvt.u32.u64 %0, t; }" : "=r"(a) : "l"(p));
    return a;
}
#define CP_ASYNC16(dst, src) \
    asm volatile("cp.async.cg.shared.global [%0], [%1], 16;" :: "r"(dst), "l"(src))
#define CP_COMMIT()  asm volatile("cp.async.commit_group;")
#define CP_WAIT1()   asm volatile("cp.async.wait_group 1;")

__device__ __forceinline__ void ldm_x4(uint32_t* r, uint32_t addr) {
    asm volatile("ldmatrix.sync.aligned.m8n8.x4.shared.b16 {%0,%1,%2,%3}, [%4];"
                 : "=r"(r[0]), "=r"(r[1]), "=r"(r[2]), "=r"(r[3]) : "r"(addr));
}
__device__ __forceinline__ void mma16816(float* d, const uint32_t* a, uint32_t b0, uint32_t b1) {
    asm volatile("mma.sync.aligned.m16n8k16.row.col.f32.f16.f16.f32 "
                 "{%0,%1,%2,%3}, {%4,%5,%6,%7}, {%8,%9}, {%0,%1,%2,%3};"
                 : "+f"(d[0]), "+f"(d[1]), "+f"(d[2]), "+f"(d[3])
                 : "r"(a[0]), "r"(a[1]), "r"(a[2]), "r"(a[3]), "r"(b0), "r"(b1));
}

// ---------------- Prep: pad + fp16 + permuted 16-channel pack ----------------
__global__ __launch_bounds__(256) void pack_kernel(const float* __restrict__ x) {
    const int wg = blockIdx.x;   // window 0..7
    const int b  = blockIdx.y;   // 0..31
    const float* xb = x + ((size_t)b * 128 + wg * 16) * HW_;
    uint32_t* dst = (uint32_t*)(g_xq + ((size_t)(b * 8 + wg)) * 3364 * 16);
    const int P[16] = {0, 1, 8, 9, 2, 3, 10, 11, 4, 5, 12, 13, 6, 7, 14, 15};
    for (int i = threadIdx.x; i < 3364; i += 256) {
        int r = i / 58;
        int c = i - r * 58;
        bool in = ((unsigned)(r - 1) < 56u) && ((unsigned)(c - 1) < 56u);
        int q = (r - 1) * 56 + (c - 1);
        uint32_t v[8];
#pragma unroll
        for (int s = 0; s < 8; s++) {
            float f0 = in ? xb[(size_t)P[2 * s] * HW_ + q] : 0.f;
            float f1 = in ? xb[(size_t)P[2 * s + 1] * HW_ + q] : 0.f;
            __half2 hp = __floats2half2_rn(f0, f1);
            v[s] = *(uint32_t*)&hp;
        }
        uint4 u0 = make_uint4(v[0], v[1], v[2], v[3]);
        uint4 u1 = make_uint4(v[4], v[5], v[6], v[7]);
        *(uint4*)(dst + (size_t)i * 8)     = u0;
        *(uint4*)(dst + (size_t)i * 8 + 4) = u1;
    }
}

// ---------------- Kernel A: build W_eff -> fp16, tap-major k ----------------
__global__ __launch_bounds__(256) void build_weff_kernel(
    const float* __restrict__ wspec,   // [8][128][1152] (cdd = c*9 + tap)
    const float* __restrict__ wch)     // [8][128][256]
{
    const int e  = blockIdx.y;
    const int n0 = blockIdx.x * 128;

    __shared__ float As[8][128];
    __shared__ float Bs[8][128];

    const int t  = threadIdx.x;
    const int tm = t >> 4;
    const int tn = t & 15;

    float acc[8][8];
#pragma unroll
    for (int i = 0; i < 8; i++)
#pragma unroll
        for (int j = 0; j < 8; j++) acc[i][j] = 0.f;

    for (int kt = 0; kt < 16; ++kt) {
#pragma unroll
        for (int i = 0; i < 4; i++) {
            int idx = t + i * 256;
            int kl  = idx >> 7;
            int nl  = idx & 127;
            As[kl][nl] = wspec[(e * 128 + kt * 8 + kl) * 1152 + n0 + nl];
            Bs[kl][nl] = wch[(e * 128 + nl) * 256 + 128 + kt * 8 + kl];
        }
        __syncthreads();
#pragma unroll
        for (int kk = 0; kk < 8; kk++) {
            float a[8], bv[8];
            *(float4*)&a[0]  = *(const float4*)&As[kk][tm * 4];
            *(float4*)&a[4]  = *(const float4*)&As[kk][64 + tm * 4];
            *(float4*)&bv[0] = *(const float4*)&Bs[kk][tn * 4];
            *(float4*)&bv[4] = *(const float4*)&Bs[kk][64 + tn * 4];
#pragma unroll
            for (int i = 0; i < 8; i++)
#pragma unroll
                for (int j = 0; j < 8; j++) acc[i][j] += a[i] * bv[j];
        }
        __syncthreads();
    }

#pragma unroll
    for (int mi = 0; mi < 8; mi++) {
        int mrow = (mi < 4) ? (tm * 4 + mi) : (64 + tm * 4 + mi - 4);
        int cdd  = n0 + mrow;
        int cc   = cdd / 9;
        int tap  = cdd - cc * 9;
        bool center = (tap == 4);
        int kidx = tap * 128 + cc;
#pragma unroll
        for (int j = 0; j < 8; j++) {
            int o = (j < 4) ? (tn * 4 + j) : (64 + tn * 4 + j - 4);
            float v = acc[mi][j];
            if (center) v += wch[(e * 128 + o) * 256 + cc];
            g_Wh[((size_t)(e * 128 + o)) * KTOT_ + kidx] = __float2half_rn(v);
        }
    }
}

// ---------------- Kernel B: fp16 mma.sync, expert-paired CTAs, 3-stage ----------------
// smem per stage:
//   A[expert 0..1]: 128 rows x 80 B = 10240 B each  -> 20480
//   B (shared):     [window kh2 (2)][px 112][16 permuted halves] -> 7168
#define A_BYTES   10240
#define B_BYTES   7168
#define BUF_BYTES (2 * A_BYTES + B_BYTES)            // 27648
#define NSTAGE    3
#define SMEM_TOTAL (NSTAGE * BUF_BYTES)              // 82944
#define A_OFF(buf, ex) ((buf) * BUF_BYTES + (ex) * A_BYTES)
#define B_OFF(buf)     ((buf) * BUF_BYTES + 20480)

__global__ __launch_bounds__(512, 1) void conv_mma_kernel(
    const int* __restrict__ gate,     // [32][2]
    float*     __restrict__ out)      // [32][2][128][56][56]
{
    extern __shared__ char smem[];
    const uint32_t sb = smem_u32(smem);

    const int tid  = threadIdx.x;
    const int wid  = tid >> 5;
    const int lane = tid & 31;
    const int g    = lane >> 2;
    const int tq   = lane & 3;
    const int b    = blockIdx.y;
    const int n0   = blockIdx.x * NPIX_;
    const int h0   = blockIdx.x * 2;

    const int ex   = wid >> 3;            // this warp's gate column
    const int e0   = gate[2 * b];
    const int e1   = gate[2 * b + 1];

    const __half* xqb = g_xq + (size_t)b * 8 * 3364 * 16;

    // warp tile within its expert half: 32(o) x 56(p)
    const int wg = wid & 7;
    const int mo = (wg >> 1) * 32;
    const int po = (wg & 1) * 56;

    float acc[2][7][4];
#pragma unroll
    for (int mt = 0; mt < 2; mt++)
#pragma unroll
        for (int j = 0; j < 7; j++)
#pragma unroll
            for (int q = 0; q < 4; q++) acc[mt][j][q] = 0.f;

    // B-fill coordinates: 448 active threads, 1 cp.async16 each
    const bool fv  = (tid < 448);
    const int fw   = tid / 224;            // window (kh2 half) 0/1
    const int fr   = tid - fw * 224;
    const int fpx  = fr >> 1;
    const int fh   = fr & 1;
    const int fpr  = (fpx >= 56);
    const int fpw  = fpx - 56 * fpr;

    auto fillStage = [&](int buf, int ch) {
        const int tap = ch >> 2;
        const int c0  = (ch & 3) << 5;
        const int kb  = tap * 128 + c0;
        // A: 1024 cp.async16 (2 experts x 128 o x 4 segs), 2 per thread
#pragma unroll
        for (int i = 0; i < 2; i++) {
            int idx = tid + i * 512;          // 0..1023
            int ae  = idx >> 9;
            int rem = idx & 511;
            int o   = rem >> 2;
            int seg = rem & 3;
            int we  = ae ? e1 : e0;
            const __half* src = g_Wh + (size_t)(we * 128 + o) * KTOT_ + kb + seg * 8;
            uint32_t dst = sb + A_OFF(buf, ae) + o * 80 + seg * 16;
            CP_ASYNC16(dst, src);
        }
        // B: 448 cp.async16
        if (fv) {
            const int dy  = tap / 3;
            const int dx  = tap - 3 * dy;
            const int poff = (h0 + fpr + dy) * 58 + (fpw + dx);
            const int w16  = ((ch & 3) << 1) + fw;
            const __half* src = xqb + ((size_t)w16 * 3364 + poff) * 16 + fh * 8;
            uint32_t d = sb + B_OFF(buf) + fw * 3584 + fpx * 32 + fh * 16;
            CP_ASYNC16(d, src);
        }
    };

    // ---- prologue: stages 0 and 1 ----
    fillStage(0, 0);
    CP_COMMIT();
    fillStage(1, 1);
    CP_COMMIT();

    int buf = 0;
    for (int ch = 0; ch < NCHUNK; ++ch) {
        CP_WAIT1();            // stage ch complete (1 newer group may remain)
        __syncthreads();       // visibility + guards refill of reused buffer

        if (ch + 2 < NCHUNK) fillStage((buf + 2 >= NSTAGE) ? buf + 2 - NSTAGE : buf + 2, ch + 2);
        CP_COMMIT();           // uniform group count (empty at tail)

        // ---- compute on buf ----
        const char* Bb = smem + B_OFF(buf);
        const uint32_t aRow = (mo + (lane & 15)) * 80 + ((lane >> 4) * 16);

#pragma unroll
        for (int kh2 = 0; kh2 < 2; kh2++) {
            uint32_t a_h[2][4];
#pragma unroll
            for (int mt = 0; mt < 2; mt++) {
                uint32_t ah = sb + A_OFF(buf, ex) + aRow + mt * (16 * 80) + kh2 * 32;
                ldm_x4(a_h[mt], ah);
            }
#pragma unroll
            for (int j = 0; j < 7; j++) {
                const int col = po + j * 8 + g;
                uint2 b01 = *(const uint2*)(Bb + kh2 * 3584 + col * 32 + tq * 8);
#pragma unroll
                for (int mt = 0; mt < 2; mt++)
                    mma16816(acc[mt][j], a_h[mt], b01.x, b01.y);
            }
        }

        buf = (buf + 1 >= NSTAGE) ? 0 : buf + 1;
    }

    // ---- epilogue ----
    float* ob = out + (size_t)(2 * b + ex) * 128 * HW_;
#pragma unroll
    for (int mt = 0; mt < 2; mt++) {
#pragma unroll
        for (int j = 0; j < 7; j++) {
            int pc = n0 + po + j * 8 + tq * 2;
            int row0 = mo + mt * 16 + g;
            float2 v0 = make_float2(acc[mt][j][0], acc[mt][j][1]);
            float2 v1 = make_float2(acc[mt][j][2], acc[mt][j][3]);
            *(float2*)(ob + (size_t)row0 * HW_ + pc) = v0;
            *(float2*)(ob + (size_t)(row0 + 8) * HW_ + pc) = v1;
        }
    }
}

// ----------------------------------------------------------------------------
extern "C" void kernel_launch(void* const* d_in, const int* in_sizes, int n_in,
                              void* d_out, int out_size) {
    const float* x     = (const float*)d_in[0];   // [32,128,56,56] f32
    const int*   gate  = (const int*)  d_in[1];   // [32,2] i32
    const float* wspec = (const float*)d_in[2];   // [8,128,128,3,3] f32
    const float* wch   = (const float*)d_in[3];   // [8,128,256,1,1] f32
    float* out = (float*)d_out;                   // [32,2,128,56,56] f32

    cudaFuncSetAttribute(conv_mma_kernel,
                         cudaFuncAttributeMaxDynamicSharedMemorySize, SMEM_TOTAL);

    pack_kernel<<<dim3(8, 32), 256>>>(x);
    build_weff_kernel<<<dim3(9, 8), 256>>>(wspec, wch);
    conv_mma_kernel<<<dim3(28, 32), 512, SMEM_TOTAL>>>(gate, out);
}

// round 9
// speedup vs baseline: 1.7410x; 1.1346x over previous
#include <cuda_runtime.h>
#include <cuda_fp16.h>
#include <cstdint>

#define HW_    3136
#define KTOT_  1152
#define NCHUNK 36          // 9 taps * 4 c-chunks of 32
#define NPIX_  112         // pixels per block tile = 2 image rows

// W in smem-image layout: [e][tap][chunk4][o 128][4 segs x 8 halves], seg pre-swizzled
__device__ __align__(16) __half g_Wq[8 * 9 * 4 * 128 * 32];
// packed x: [b][window (8 of 16ch)][58*58 px][16 halves, permuted {0,1,8,9,2,3,10,11,4,5,12,13,6,7,14,15}]
__device__ __align__(16) __half g_xq[(size_t)32 * 8 * 3364 * 16];

__device__ __forceinline__ uint32_t smem_u32(const void* p) {
    uint32_t a;
    asm("{ .reg .u64 t; cvta.to.shared.u64 t, %1; cvt.u32.u64 %0, t; }" : "=r"(a) : "l"(p));
    return a;
}
#define MBAR_INIT(mb, c)  asm volatile("mbarrier.init.shared.b64 [%0], %1;" :: "r"(mb), "r"(c) : "memory")
#define MBAR_EXPECT(mb, tx) \
    asm volatile("mbarrier.arrive.expect_tx.shared.b64 _, [%0], %1;" :: "r"(mb), "r"(tx) : "memory")
#define BULK_G2S(dst, src, sz, mb) \
    asm volatile("cp.async.bulk.shared::cta.global.mbarrier::complete_tx::bytes [%0], [%1], %2, [%3];" \
                 :: "r"(dst), "l"(src), "r"(sz), "r"(mb) : "memory")

#define MBAR_WAIT(mb, ph) do {                                                            \
    uint32_t _m = (mb), _p = (ph), _d;                                                    \
    asm volatile("{ .reg .pred p; mbarrier.try_wait.parity.acquire.cta.shared::cta.b64 "  \
                 "p, [%1], %2; selp.b32 %0, 1, 0, p; }"                                   \
                 : "=r"(_d) : "r"(_m), "r"(_p) : "memory");                               \
    if (!_d) {                                                                            \
        asm volatile("{ .reg .pred P1;\n\t"                                               \
            "W_%=: mbarrier.try_wait.parity.acquire.cta.shared::cta.b64 P1, [%0], %1, 0x989680;\n\t" \
            "@P1 bra.uni D_%=;\n\t bra.uni W_%=;\n\t D_%=: }"                             \
            :: "r"(_m), "r"(_p) : "memory");                                              \
    } } while (0)

__device__ __forceinline__ void ldm_x4(uint32_t* r, uint32_t addr) {
    asm volatile("ldmatrix.sync.aligned.m8n8.x4.shared.b16 {%0,%1,%2,%3}, [%4];"
                 : "=r"(r[0]), "=r"(r[1]), "=r"(r[2]), "=r"(r[3]) : "r"(addr));
}
__device__ __forceinline__ void mma16816(float* d, const uint32_t* a, uint32_t b0, uint32_t b1) {
    asm volatile("mma.sync.aligned.m16n8k16.row.col.f32.f16.f16.f32 "
                 "{%0,%1,%2,%3}, {%4,%5,%6,%7}, {%8,%9}, {%0,%1,%2,%3};"
                 : "+f"(d[0]), "+f"(d[1]), "+f"(d[2]), "+f"(d[3])
                 : "r"(a[0]), "r"(a[1]), "r"(a[2]), "r"(a[3]), "r"(b0), "r"(b1));
}

// ---------------- Prep: pad + fp16 + permuted 16-channel pack ----------------
__global__ __launch_bounds__(256) void pack_kernel(const float* __restrict__ x) {
    const int wg = blockIdx.x;   // window 0..7
    const int b  = blockIdx.y;   // 0..31
    const float* xb = x + ((size_t)b * 128 + wg * 16) * HW_;
    uint32_t* dst = (uint32_t*)(g_xq + ((size_t)(b * 8 + wg)) * 3364 * 16);
    const int P[16] = {0, 1, 8, 9, 2, 3, 10, 11, 4, 5, 12, 13, 6, 7, 14, 15};
    for (int i = threadIdx.x; i < 3364; i += 256) {
        int r = i / 58;
        int c = i - r * 58;
        bool in = ((unsigned)(r - 1) < 56u) && ((unsigned)(c - 1) < 56u);
        int q = (r - 1) * 56 + (c - 1);
        uint32_t v[8];
#pragma unroll
        for (int s = 0; s < 8; s++) {
            float f0 = in ? xb[(size_t)P[2 * s] * HW_ + q] : 0.f;
            float f1 = in ? xb[(size_t)P[2 * s + 1] * HW_ + q] : 0.f;
            __half2 hp = __floats2half2_rn(f0, f1);
            v[s] = *(uint32_t*)&hp;
        }
        *(uint4*)(dst + (size_t)i * 8)     = make_uint4(v[0], v[1], v[2], v[3]);
        *(uint4*)(dst + (size_t)i * 8 + 4) = make_uint4(v[4], v[5], v[6], v[7]);
    }
}

// ---------------- Kernel A: build W_eff -> fp16, smem-image layout ----------------
__global__ __launch_bounds__(256) void build_weff_kernel(
    const float* __restrict__ wspec,   // [8][128][1152] (cdd = c*9 + tap)
    const float* __restrict__ wch)     // [8][128][256]
{
    const int e  = blockIdx.y;
    const int n0 = blockIdx.x * 128;

    __shared__ float As[8][128];
    __shared__ float Bs[8][128];

    const int t  = threadIdx.x;
    const int tm = t >> 4;
    const int tn = t & 15;

    float acc[8][8];
#pragma unroll
    for (int i = 0; i < 8; i++)
#pragma unroll
        for (int j = 0; j < 8; j++) acc[i][j] = 0.f;

    for (int kt = 0; kt < 16; ++kt) {
#pragma unroll
        for (int i = 0; i < 4; i++) {
            int idx = t + i * 256;
            int kl  = idx >> 7;
            int nl  = idx & 127;
            As[kl][nl] = wspec[(e * 128 + kt * 8 + kl) * 1152 + n0 + nl];
            Bs[kl][nl] = wch[(e * 128 + nl) * 256 + 128 + kt * 8 + kl];
        }
        __syncthreads();
#pragma unroll
        for (int kk = 0; kk < 8; kk++) {
            float a[8], bv[8];
            *(float4*)&a[0]  = *(const float4*)&As[kk][tm * 4];
            *(float4*)&a[4]  = *(const float4*)&As[kk][64 + tm * 4];
            *(float4*)&bv[0] = *(const float4*)&Bs[kk][tn * 4];
            *(float4*)&bv[4] = *(const float4*)&Bs[kk][64 + tn * 4];
#pragma unroll
            for (int i = 0; i < 8; i++)
#pragma unroll
                for (int j = 0; j < 8; j++) acc[i][j] += a[i] * bv[j];
        }
        __syncthreads();
    }

#pragma unroll
    for (int mi = 0; mi < 8; mi++) {
        int mrow = (mi < 4) ? (tm * 4 + mi) : (64 + tm * 4 + mi - 4);
        int cdd  = n0 + mrow;
        int cc   = cdd / 9;               // channel
        int tap  = cdd - cc * 9;
        bool center = (tap == 4);
        int chunk = cc >> 5;
        int pos   = cc & 31;
        int seg   = pos >> 3;
        int w8    = pos & 7;
#pragma unroll
        for (int j = 0; j < 8; j++) {
            int o = (j < 4) ? (tn * 4 + j) : (64 + tn * 4 + j - 4);
            float v = acc[mi][j];
            if (center) v += wch[(e * 128 + o) * 256 + cc];
            int segS = seg ^ ((o >> 1) & 3);   // ldmatrix bank swizzle, pre-baked
            size_t idx = ((((size_t)(e * 9 + tap) * 4 + chunk) * 128 + o) * 4 + segS) * 8 + w8;
            g_Wq[idx] = __float2half_rn(v);
        }
    }
}

// ---------------- Kernel B: fp16 mma.sync, cp.async.bulk fills ----------------
// smem per stage slot:
//   A[expert 0..1]: 128 o x 64 B (pre-swizzled)  -> 8192 each, 16384
//   B: [kh2-half (2)][px 112][16 halves]         -> 7168
#define A_SZ      8192
#define B_SZ      7168
#define SLOT_SZ   (2 * A_SZ + B_SZ)               // 23552
#define NSTAGE    3
#define SMEM_TOTAL (1024 + NSTAGE * SLOT_SZ)      // 71680
#define A_OFF(buf, ex) (1024 + (buf) * SLOT_SZ + (ex) * A_SZ)
#define B_OFF(buf)     (1024 + (buf) * SLOT_SZ + 16384)

__global__ __launch_bounds__(512, 1) void conv_mma_kernel(
    const int* __restrict__ gate,     // [32][2]
    float*     __restrict__ out)      // [32][2][128][56][56]
{
    extern __shared__ char smem[];
    const uint32_t sb = smem_u32(smem);

    const int tid  = threadIdx.x;
    const int wid  = tid >> 5;
    const int lane = tid & 31;
    const int g    = lane >> 2;
    const int tq   = lane & 3;
    const int b    = blockIdx.y;
    const int n0   = blockIdx.x * NPIX_;
    const int h0   = blockIdx.x * 2;

    const int ex   = wid >> 3;            // this warp's gate column
    const int e0   = gate[2 * b];
    const int e1   = gate[2 * b + 1];

    const __half* xqb = g_xq + (size_t)b * 8 * 3364 * 16;

    // warp tile within its expert half: 32(o) x 56(p)
    const int wg = wid & 7;
    const int mo = (wg >> 1) * 32;
    const int po = (wg & 1) * 56;

    float acc[2][7][4];
#pragma unroll
    for (int mt = 0; mt < 2; mt++)
#pragma unroll
        for (int j = 0; j < 7; j++)
#pragma unroll
            for (int q = 0; q < 4; q++) acc[mt][j][q] = 0.f;

    // mbarriers at sb + 8*slot
    if (tid == 0) {
        MBAR_INIT(sb + 0, 1);
        MBAR_INIT(sb + 8, 1);
        MBAR_INIT(sb + 16, 1);
    }
    __syncthreads();

    // producer: tid 0 issues 6 bulk copies per stage
    auto fillStage = [&](int buf, int ch) {
        const int tap = ch >> 2;
        const int cc  = ch & 3;
        const uint32_t mb = sb + 8 * buf;
        MBAR_EXPECT(mb, (uint32_t)SLOT_SZ);
        // A: one 8 KB bulk per expert
        const __half* a0 = g_Wq + (((size_t)(e0 * 9 + tap) * 4 + cc) * 128) * 32;
        const __half* a1 = g_Wq + (((size_t)(e1 * 9 + tap) * 4 + cc) * 128) * 32;
        BULK_G2S(sb + A_OFF(buf, 0), a0, A_SZ, mb);
        BULK_G2S(sb + A_OFF(buf, 1), a1, A_SZ, mb);
        // B: 4 bulk copies of 1792 B (2 kh2 windows x 2 image rows)
        const int dy = tap / 3;
        const int dx = tap - 3 * dy;
#pragma unroll
        for (int fw = 0; fw < 2; fw++) {
            const int w16 = cc * 2 + fw;
#pragma unroll
            for (int r = 0; r < 2; r++) {
                const int poff = (h0 + dy + r) * 58 + dx;
                const __half* src = xqb + ((size_t)w16 * 3364 + poff) * 16;
                BULK_G2S(sb + B_OFF(buf) + fw * 3584 + r * 1792, src, 1792, mb);
            }
        }
    };

    if (tid == 0) {
        fillStage(0, 0);
        fillStage(1, 1);
    }

    int phase[NSTAGE] = {0, 0, 0};
    int buf = 0;
    for (int ch = 0; ch < NCHUNK; ++ch) {
        MBAR_WAIT(sb + 8 * buf, phase[buf]);
        phase[buf] ^= 1;
        __syncthreads();     // all threads done with slot (buf+2)%3 from iteration ch-1

        if (tid == 0 && ch + 2 < NCHUNK)
            fillStage((buf + 2 >= NSTAGE) ? buf + 2 - NSTAGE : buf + 2, ch + 2);

        // ---- compute on buf ----
        const char* Bb = smem + B_OFF(buf);
        const uint32_t aBase = sb + A_OFF(buf, ex);
        const int orow = lane & 15;
        const int chalf = lane >> 4;

#pragma unroll
        for (int kh2 = 0; kh2 < 2; kh2++) {
            uint32_t a_h[2][4];
#pragma unroll
            for (int mt = 0; mt < 2; mt++) {
                int o = mo + mt * 16 + orow;
                int s = kh2 * 2 + chalf;
                uint32_t ah = aBase + o * 64 + ((s ^ ((o >> 1) & 3)) << 4);
                ldm_x4(a_h[mt], ah);
            }
#pragma unroll
            for (int j = 0; j < 7; j++) {
                const int col = po + j * 8 + g;
                uint2 b01 = *(const uint2*)(Bb + kh2 * 3584 + col * 32 + tq * 8);
#pragma unroll
                for (int mt = 0; mt < 2; mt++)
                    mma16816(acc[mt][j], a_h[mt], b01.x, b01.y);
            }
        }

        buf = (buf + 1 >= NSTAGE) ? 0 : buf + 1;
    }

    // ---- epilogue ----
    float* ob = out + (size_t)(2 * b + ex) * 128 * HW_;
#pragma unroll
    for (int mt = 0; mt < 2; mt++) {
#pragma unroll
        for (int j = 0; j < 7; j++) {
            int pc = n0 + po + j * 8 + tq * 2;
            int row0 = mo + mt * 16 + g;
            float2 v0 = make_float2(acc[mt][j][0], acc[mt][j][1]);
            float2 v1 = make_float2(acc[mt][j][2], acc[mt][j][3]);
            *(float2*)(ob + (size_t)row0 * HW_ + pc) = v0;
            *(float2*)(ob + (size_t)(row0 + 8) * HW_ + pc) = v1;
        }
    }
}

// ----------------------------------------------------------------------------
extern "C" void kernel_launch(void* const* d_in, const int* in_sizes, int n_in,
                              void* d_out, int out_size) {
    const float* x     = (const float*)d_in[0];   // [32,128,56,56] f32
    const int*   gate  = (const int*)  d_in[1];   // [32,2] i32
    const float* wspec = (const float*)d_in[2];   // [8,128,128,3,3] f32
    const float* wch   = (const float*)d_in[3];   // [8,128,256,1,1] f32
    float* out = (float*)d_out;                   // [32,2,128,56,56] f32

    cudaFuncSetAttribute(conv_mma_kernel,
                         cudaFuncAttributeMaxDynamicSharedMemorySize, SMEM_TOTAL);

    pack_kernel<<<dim3(8, 32), 256>>>(x);
    build_weff_kernel<<<dim3(9, 8), 256>>>(wspec, wch);
    conv_mma_kernel<<<dim3(28, 32), 512, SMEM_TOTAL>>>(gate, out);
}